// round 17
// baseline (speedup 1.0000x reference)
#include <cuda_runtime.h>
#include <cstdint>

// ============================================================================
// PillarFeatureNet — fused single-pass + streaming epilogue (R15-proven
// structure) with head prefetch in phase A and a wide-load epilogue.
//
// k_fused: per voxel computes global moments AND per-channel extreme of the
//   raw sign-folded 4->64 linear (sign(sc)=sign(gamma) known pre-statistics);
//   head prefetch (npts, vox, px/py) hides the dependent-LDG chain. Last
//   block finalizes (|sc|, sh) per channel and self-resets for graph replay.
// k_post: warp = 2 voxels, lane handles 4 channels via float4 ext/out;
//   out = k>0 ? relu(|sc|·ext + sh) : 0.
// ============================================================================

#define MAX_N 60000
#define BLOCK 256
#define GRID1 592              /* 148 SMs * 4 blocks (fused, 64-reg cap) */
#define GRID2 888
#define NWARP (BLOCK / 32)
#define NSTAT 54

__device__ float    g_stats[NSTAT];
__device__ unsigned g_count;
__device__ float4   g_scsh[32];          // idx -> (|sc|,sh) for channels 2i,2i+1
__device__ float2   g_ext[MAX_N * 32];   // per-voxel per-lane channel-pair extremes

// distributed per-voxel scalar terms (R15-proven tables). q vector (smem,16):
// [0..2]=m [3..5]=sa [6]=px [7]=py [8]=kpx [9]=kpy [10]=1 [11..14]=sv [15]=0
__constant__ unsigned char cA[64] = {
    11,12,13,14,  0,0,0,0, 1,1,1,1, 2,2,2,2,  6,6,6,6,  7,7,7,7,
    3,3,3,4,4,5,  3,4,
    5, 3,4,5, 3,4,5, 8,8,9, 8,9,
    15,15,15,15,15,15,15,15,15,15,15,15,15,15,15,15,15,15,15,15};
__constant__ unsigned char cB[64] = {
    10,10,10,10,  11,12,13,14, 11,12,13,14, 11,12,13,14,  11,12,13,14,  11,12,13,14,
    0,1,2,1,2,2,  6,6,
    6, 7,7,7, 10,10,10, 6,7,7, 10,10,
    15,15,15,15,15,15,15,15,15,15,15,15,15,15,15,15,15,15,15,15};

__device__ __forceinline__ float wsum(float x) {
#pragma unroll
    for (int o = 16; o; o >>= 1) x += __shfl_xor_sync(0xffffffffu, x, o);
    return x;
}

// ---------------------------------------------------------------------------
// Fused kernel (phase A head-prefetched)
// ---------------------------------------------------------------------------
__global__ void __launch_bounds__(BLOCK, 4) k_fused(
    const float4* __restrict__ vox, const int* __restrict__ npts,
    const int4* __restrict__ coors, const float* __restrict__ Wm,
    const float* __restrict__ gm, const float* __restrict__ bt,
    float invNP, int N)
{
    const int lane = threadIdx.x & 31;
    const int wid  = threadIdx.x >> 5;
    const int warp = blockIdx.x * NWARP + wid;
    const int nwarps = GRID1 * NWARP;

    __shared__ float  q_sm[NWARP][16];
    __shared__ float  red[NWARP][NSTAT];
    __shared__ __align__(8) float2 sA2[4][32];
    __shared__ __align__(8) float2 sB2[5][32];
    __shared__ __align__(16) float4 pts[NWARP][32];

    // sign-folded raw coefficient tables (inputs only)
    if (threadIdx.x < 64) {
        const int o = threadIdx.x;
        float w[9];
#pragma unroll
        for (int j = 0; j < 9; j++) w[j] = Wm[o * 9 + j];
        const float s = (gm[o] < 0.0f) ? -1.0f : 1.0f;
        ((float*)sA2[0])[o] = s * (w[0] + w[4] + w[7]);
        ((float*)sA2[1])[o] = s * (w[1] + w[5] + w[8]);
        ((float*)sA2[2])[o] = s * (w[2] + w[6]);
        ((float*)sA2[3])[o] = s * w[3];
        ((float*)sB2[0])[o] = s * w[4];
        ((float*)sB2[1])[o] = s * w[5];
        ((float*)sB2[2])[o] = s * w[6];
        ((float*)sB2[3])[o] = s * w[7];
        ((float*)sB2[4])[o] = s * w[8];
    }
    __syncthreads();

    const float2 A0 = sA2[0][lane], A1 = sA2[1][lane];
    const float2 A2 = sA2[2][lane], A3 = sA2[3][lane];

    float a[10];
#pragma unroll
    for (int i = 0; i < 10; i++) a[i] = 0.0f;
    float pv0 = 0.0f, pv1 = 0.0f;
    const int iA0 = cA[lane],      iB0 = cB[lane];
    const int iA1 = cA[32 + lane], iB1 = cB[32 + lane];

    const float NEG_INF = __int_as_float(0xff800000);
    const float QNAN    = __int_as_float(0x7fffffff);

    // head prefetch state
    int    pre_k  = 0;
    float4 pre_v  = make_float4(0.f, 0.f, 0.f, 0.f);
    float  pre_px = 0.0f, pre_py = 0.0f;
    int n = warp;
    if (n < N) {
        pre_k = __ldg(&npts[n]);
        pre_v = vox[(size_t)n * 32 + lane];
        const int4 cc = coors[n];
        pre_px = (float)cc.y * 0.1f + (0.05f - 20.0f);
        pre_py = (float)cc.z * 0.1f + (0.05f - 20.0f);
    }

    for (; n < N; n += nwarps) {
        const int k = pre_k;
        const float4 v = pre_v;
        const float px = pre_px, py = pre_py;
        const int n2 = n + nwarps;
        if (n2 < N) {
            pre_k = __ldg(&npts[n2]);
            pre_v = vox[(size_t)n2 * 32 + lane];
            const int4 cc = coors[n2];
            pre_px = (float)cc.y * 0.1f + (0.05f - 20.0f);
            pre_py = (float)cc.z * 0.1f + (0.05f - 20.0f);
        }
        if (k == 0) continue;                          // k_post zeroes these

        float4 uz = v;                                 // zero-masked (moments)
        if (lane >= k) { uz.x = 0.f; uz.y = 0.f; uz.z = 0.f; uz.w = 0.f; }

        a[0] += uz.x * uz.x;  a[1] += uz.x * uz.y;  a[2] += uz.x * uz.z;  a[3] += uz.x * uz.w;
        a[4] += uz.y * uz.y;  a[5] += uz.y * uz.z;  a[6] += uz.y * uz.w;
        a[7] += uz.z * uz.z;  a[8] += uz.z * uz.w;  a[9] += uz.w * uz.w;

        const float sa0 = wsum(v.x),  sa1 = wsum(v.y),  sa2 = wsum(v.z);
        const float sv0 = wsum(uz.x), sv1 = wsum(uz.y), sv2 = wsum(uz.z), sv3 = wsum(uz.w);
        const float kf = (float)k, inv = 1.0f / kf;
        const float m0 = sa0 * inv, m1 = sa1 * inv, m2 = sa2 * inv;

        if (lane == 0) {
            float4* qs = (float4*)q_sm[wid];
            qs[0] = make_float4(m0, m1, m2, sa0);
            qs[1] = make_float4(sa1, sa2, px, py);
            qs[2] = make_float4(kf * px, kf * py, 1.0f, sv0);
            qs[3] = make_float4(sv1, sv2, sv3, 0.0f);
        }
        float4 un = v;                                 // NaN-masked (extremes)
        if (lane >= k) { un.x = QNAN; un.y = QNAN; un.z = QNAN; un.w = QNAN; }
        pts[wid][lane] = un;
        __syncwarp();
        pv0 = fmaf(q_sm[wid][iA0], q_sm[wid][iB0], pv0);
        pv1 = fmaf(q_sm[wid][iA1], q_sm[wid][iB1], pv1);

        const float2 B0 = sB2[0][lane], B1 = sB2[1][lane], B2 = sB2[2][lane];
        const float2 B3 = sB2[3][lane], B4 = sB2[4][lane];
        float ta = B0.x * m0;
        ta = fmaf(B1.x, m1, ta); ta = fmaf(B2.x, m2, ta);
        ta = fmaf(B3.x, px, ta); ta = fmaf(B4.x, py, ta);
        const float offa = -ta;
        float tb = B0.y * m0;
        tb = fmaf(B1.y, m1, tb); tb = fmaf(B2.y, m2, tb);
        tb = fmaf(B3.y, px, tb); tb = fmaf(B4.y, py, tb);
        const float offb = -tb;

        float ra = NEG_INF, rb = NEG_INF;
        const int k2 = (k + 1) >> 1;
#pragma unroll 2
        for (int j = 0; j < k2; j++) {
            const float4 u0 = pts[wid][2 * j];
            const float4 u1 = pts[wid][2 * j + 1];
            const float y0a = fmaf(u0.x, A0.x, fmaf(u0.y, A1.x, fmaf(u0.z, A2.x, fmaf(u0.w, A3.x, offa))));
            const float y0b = fmaf(u0.x, A0.y, fmaf(u0.y, A1.y, fmaf(u0.z, A2.y, fmaf(u0.w, A3.y, offb))));
            const float y1a = fmaf(u1.x, A0.x, fmaf(u1.y, A1.x, fmaf(u1.z, A2.x, fmaf(u1.w, A3.x, offa))));
            const float y1b = fmaf(u1.x, A0.y, fmaf(u1.y, A1.y, fmaf(u1.z, A2.y, fmaf(u1.w, A3.y, offb))));
            ra = fmaxf(fmaxf(ra, y0a), y1a);
            rb = fmaxf(fmaxf(rb, y0b), y1b);
        }
        g_ext[(size_t)n * 32 + lane] = make_float2(ra, rb);
        __syncwarp();
    }

    // ---- stats reduction ----
#pragma unroll
    for (int i = 0; i < 10; i++) a[i] = wsum(a[i]);
    {
        const int d0 = (lane < 4) ? lane : lane + 10;
        red[wid][d0] = pv0;                       // stats 0..3, 14..41
        if (lane < 12) red[wid][42 + lane] = pv1; // stats 42..53
        if (lane == 0) {
#pragma unroll
            for (int i = 0; i < 10; i++) red[wid][4 + i] = a[i];  // G2
        }
    }
    __syncthreads();
    if (threadIdx.x < NSTAT) {
        float s = 0.0f;
#pragma unroll
        for (int w = 0; w < NWARP; w++) s += red[w][threadIdx.x];
        atomicAdd(&g_stats[threadIdx.x], s);
    }
    __threadfence();
    __shared__ unsigned s_last;
    if (threadIdx.x == 0) s_last = atomicAdd(&g_count, 1u);
    __syncthreads();
    if (s_last != GRID1 - 1) return;
    __threadfence();

    // ---------------- finalize (last block only) ----------------
    __shared__ float S[9];
    __shared__ float M[9][9];
    if (threadIdx.x == 0) {
        float st[NSTAT];
#pragma unroll
        for (int i = 0; i < NSTAT; i++) st[i] = __ldcg(&g_stats[i]);

        auto G2f = [&](int i, int j) -> float {
            if (i > j) { int t = i; i = j; j = t; }
            const int base[4] = {0, 4, 7, 9};
            return st[4 + base[i] + (j - i)];
        };
        auto U = [&](int i, int j) -> float { return st[14 + i * 4 + j]; };
        auto V = [&](int i, int j) -> float {
            int lo = i < j ? i : j, hi = i < j ? j : i;
            const int b3[3] = {0, 3, 5};
            return st[34 + b3[lo] + (hi - lo)];
        };
        const float* Qx = st + 26; const float* Qy = st + 30;
        const float* Wx = st + 40; const float* Wy = st + 43; const float* Ksa = st + 46;
        const float Rxx = st[49], Rxy = st[50], Ryy = st[51], Lx = st[52], Ly = st[53];

        S[0] = st[0]; S[1] = st[1]; S[2] = st[2]; S[3] = st[3];
        S[4] = st[0] - Ksa[0]; S[5] = st[1] - Ksa[1]; S[6] = st[2] - Ksa[2];
        S[7] = st[0] - Lx;     S[8] = st[1] - Ly;

        for (int i = 0; i < 4; i++)
            for (int j = 0; j < 4; j++) M[i][j] = G2f(i, j);
        for (int j = 0; j < 3; j++)
            for (int i = 0; i < 4; i++) {
                const float m = G2f(i, j) - U(j, i);
                M[i][4 + j] = m; M[4 + j][i] = m;
            }
        for (int i = 0; i < 3; i++)
            for (int j = 0; j < 3; j++)
                M[4 + i][4 + j] = G2f(i, j) - U(i, j) - U(j, i) + V(i, j);
        for (int i = 0; i < 4; i++) {
            float m = G2f(i, 0) - Qx[i]; M[i][7] = m; M[7][i] = m;
            m       = G2f(i, 1) - Qy[i]; M[i][8] = m; M[8][i] = m;
        }
        for (int i = 0; i < 3; i++) {
            float m = G2f(i, 0) - Qx[i] - U(i, 0) + Wx[i]; M[4 + i][7] = m; M[7][4 + i] = m;
            m       = G2f(i, 1) - Qy[i] - U(i, 1) + Wy[i]; M[4 + i][8] = m; M[8][4 + i] = m;
        }
        M[7][7] = G2f(0, 0) - 2.0f * Qx[0] + Rxx;
        M[7][8] = G2f(0, 1) - Qx[1] - Qy[0] + Rxy; M[8][7] = M[7][8];
        M[8][8] = G2f(1, 1) - 2.0f * Qy[1] + Ryy;
    }
    __syncthreads();

    if (threadIdx.x < NSTAT) g_stats[threadIdx.x] = 0.0f;   // replay reset
    if (threadIdx.x == 0)    g_count = 0u;

    const int o = threadIdx.x;
    __shared__ float2 scsh_tmp[64];
    if (o < 64) {
        float w[9];
#pragma unroll
        for (int j = 0; j < 9; j++) w[j] = Wm[o * 9 + j];
        float mean = 0.0f;
#pragma unroll
        for (int j = 0; j < 9; j++) mean += w[j] * S[j];
        mean *= invNP;
        float e2 = 0.0f;
#pragma unroll
        for (int i = 0; i < 9; i++) {
            float acc = 0.0f;
#pragma unroll
            for (int j = 0; j < 9; j++) acc += w[j] * M[i][j];
            e2 += w[i] * acc;
        }
        e2 *= invNP;
        const float var = e2 - mean * mean;
        const float sc  = gm[o] * rsqrtf(var + 1e-3f);
        const float sh  = bt[o] - mean * sc;
        scsh_tmp[o] = make_float2(fabsf(sc), sh);
    }
    __syncthreads();
    if (o < 32)
        g_scsh[o] = make_float4(scsh_tmp[2 * o].x, scsh_tmp[2 * o].y,
                                scsh_tmp[2 * o + 1].x, scsh_tmp[2 * o + 1].y);
}

// ---------------------------------------------------------------------------
// Post: warp = 2 voxels (half-warp each); lane handles 4 channels via one
// float4 ext load + one float4 out store; prefetched.
// out = k>0 ? relu(|sc|·ext + sh) : 0
// ---------------------------------------------------------------------------
__global__ void __launch_bounds__(BLOCK) k_post(
    const int* __restrict__ npts, float4* __restrict__ out4, int N)
{
    const int lane = threadIdx.x & 31;
    const int half = lane >> 4;            // which voxel of the pair
    const int h    = lane & 15;            // float4 slot within voxel
    const int warp = (blockIdx.x * BLOCK + threadIdx.x) >> 5;
    const int nwarps = (GRID2 * BLOCK) >> 5;

    // channels 4h..4h+3
    const float4 sA = g_scsh[2 * h];       // (sc,sh) ch 4h, 4h+1
    const float4 sBc = g_scsh[2 * h + 1];  // (sc,sh) ch 4h+2, 4h+3
    const float4* __restrict__ ext4 = (const float4*)g_ext;

    const int npairs = (N + 1) >> 1;
    int p = warp;
    int n = 2 * p + half;
    int    pk = 0;
    float4 pe = make_float4(0.f, 0.f, 0.f, 0.f);
    bool valid = (p < npairs) && (n < N);
    if (valid) { pk = __ldg(&npts[n]); pe = ext4[(size_t)n * 16 + h]; }

    for (; p < npairs; p += nwarps) {
        const int  k = pk;
        const float4 e = pe;
        const bool was_valid = valid;
        const int  n_cur = n;

        const int p2 = p + nwarps;
        n = 2 * p2 + half;
        valid = (p2 < npairs) && (n < N);
        if (valid) { pk = __ldg(&npts[n]); pe = ext4[(size_t)n * 16 + h]; }

        if (was_valid) {
            float4 o;
            if (k > 0) {
                o.x = fmaxf(fmaf(sA.x,  e.x, sA.y),  0.0f);
                o.y = fmaxf(fmaf(sA.z,  e.y, sA.w),  0.0f);
                o.z = fmaxf(fmaf(sBc.x, e.z, sBc.y), 0.0f);
                o.w = fmaxf(fmaf(sBc.z, e.w, sBc.w), 0.0f);
            } else {
                o.x = 0.0f; o.y = 0.0f; o.z = 0.0f; o.w = 0.0f;
            }
            out4[(size_t)n_cur * 16 + h] = o;
        }
    }
}

// ---------------------------------------------------------------------------
extern "C" void kernel_launch(void* const* d_in, const int* in_sizes, int n_in,
                              void* d_out, int out_size)
{
    const float* voxels = (const float*)d_in[0];
    const int*   npts   = (const int*)d_in[1];
    const int*   coors  = (const int*)d_in[2];
    const float* W      = (const float*)d_in[3];
    const float* gamma  = (const float*)d_in[4];
    const float* beta   = (const float*)d_in[5];
    float*       out    = (float*)d_out;
    const int N = in_sizes[1];

    k_fused<<<GRID1, BLOCK>>>((const float4*)voxels, npts, (const int4*)coors,
                              W, gamma, beta, 1.0f / ((float)N * 32.0f), N);
    k_post<<<GRID2, BLOCK>>>(npts, (float4*)out, N);
}